// round 1
// baseline (speedup 1.0000x reference)
#include <cuda_runtime.h>
#include <cuda_bf16.h>
#include <math.h>

#define N_NODES 200000
#define N_EDGES 6400000
#define F_IN    128
#define H1      16
#define C2      2

// ---------------- device scratch (no allocations allowed) ----------------
__device__ int   g_src[N_EDGES];
__device__ int   g_dst[N_EDGES];
__device__ float g_degf[N_NODES];
__device__ float g_dinv[N_NODES];
__device__ float g_h1[N_NODES * H1];
__device__ float g_agg1[N_NODES * H1];
__device__ float g_h2[N_NODES * C2];
__device__ float g_agg2[N_NODES * C2];
__device__ int   g_is64;

// ---------------- zero scratch accumulators ----------------
__global__ void k_zero() {
    int total = N_NODES + N_NODES * H1 + N_NODES * C2;
    for (int i = blockIdx.x * blockDim.x + threadIdx.x; i < total;
         i += gridDim.x * blockDim.x) {
        if (i < N_NODES) {
            g_degf[i] = 0.f;
        } else if (i < N_NODES + N_NODES * H1) {
            g_agg1[i - N_NODES] = 0.f;
        } else {
            g_agg2[i - N_NODES - N_NODES * H1] = 0.f;
        }
    }
}

// ---------------- detect whether edge_index is int64 or int32 ----------------
// If the buffer really holds int64 indices, the first 1024 int64 words are all
// in [0, N_NODES). If it holds int32, an int64 view combines adjacent pairs and
// is astronomically unlikely (p ~ (1/200000)^1024) to stay in range.
__global__ void k_detect(const void* ei) {
    __shared__ int bad;
    if (threadIdx.x == 0) bad = 0;
    __syncthreads();
    const long long* p = (const long long*)ei;
    for (int i = threadIdx.x; i < 1024; i += blockDim.x) {
        long long v = p[i];
        if (v < 0 || v >= (long long)N_NODES) bad = 1;
    }
    __syncthreads();
    if (threadIdx.x == 0) g_is64 = bad ? 0 : 1;
}

// ---------------- convert indices to int32 + degree count ----------------
__global__ void k_convert(const void* ei, int E) {
    int i = blockIdx.x * blockDim.x + threadIdx.x;
    if (i >= E) return;
    int s, d;
    if (g_is64) {
        const long long* p = (const long long*)ei;
        s = (int)p[i];
        d = (int)p[E + i];
    } else {
        const int* p = (const int*)ei;
        s = p[i];
        d = p[E + i];
    }
    g_src[i] = s;
    g_dst[i] = d;
    atomicAdd(&g_degf[d], 1.0f);
}

// ---------------- dinv = rsqrt(deg + 1) ----------------
__global__ void k_dinv(int n) {
    int i = blockIdx.x * blockDim.x + threadIdx.x;
    if (i >= n) return;
    g_dinv[i] = rsqrtf(g_degf[i] + 1.0f);
}

// ---------------- h1 = x @ W1 (warp per node) ----------------
__global__ void k_h1(const float* __restrict__ x, const float* __restrict__ W1,
                     int n) {
    __shared__ float W1t[H1 * F_IN];  // transposed: [j][k]
    for (int t = threadIdx.x; t < F_IN * H1; t += blockDim.x) {
        int k = t / H1, j = t % H1;
        W1t[j * F_IN + k] = W1[t];
    }
    __syncthreads();

    int warp = (blockIdx.x * blockDim.x + threadIdx.x) >> 5;
    int lane = threadIdx.x & 31;
    if (warp >= n) return;

    // one warp loads the whole 128-float row coalesced: lane -> 16B chunk
    float4 xv = ((const float4*)x)[warp * (F_IN / 4) + lane];

    float acc[H1];
#pragma unroll
    for (int j = 0; j < H1; j++) {
        float4 w = ((const float4*)W1t)[j * (F_IN / 4) + lane];
        acc[j] = xv.x * w.x + xv.y * w.y + xv.z * w.z + xv.w * w.w;
    }
#pragma unroll
    for (int off = 16; off; off >>= 1) {
#pragma unroll
        for (int j = 0; j < H1; j++)
            acc[j] += __shfl_xor_sync(0xffffffff, acc[j], off);
    }
    if (lane == 0) {
        float4* o = (float4*)(g_h1 + warp * H1);
        o[0] = make_float4(acc[0], acc[1], acc[2], acc[3]);
        o[1] = make_float4(acc[4], acc[5], acc[6], acc[7]);
        o[2] = make_float4(acc[8], acc[9], acc[10], acc[11]);
        o[3] = make_float4(acc[12], acc[13], acc[14], acc[15]);
    }
}

// ---------------- layer-1 edge scatter: agg1[dst] += norm * h1[src] ----------
__global__ void k_scatter1(int E) {
    int i = blockIdx.x * blockDim.x + threadIdx.x;
    if (i >= E) return;
    int s = g_src[i], d = g_dst[i];
    float norm = g_dinv[s] * g_dinv[d];
    const float4* h = (const float4*)(g_h1 + s * H1);
    float* out = g_agg1 + d * H1;
#pragma unroll
    for (int q = 0; q < 4; q++) {
        float4 v = h[q];
        v.x *= norm; v.y *= norm; v.z *= norm; v.w *= norm;
        asm volatile(
            "red.global.add.v4.f32 [%0], {%1, %2, %3, %4};" ::"l"(out + q * 4),
            "f"(v.x), "f"(v.y), "f"(v.z), "f"(v.w)
            : "memory");
    }
}

// ---------------- combine1 + ReLU + @W2, fused ----------------
__global__ void k_combine1(const float* __restrict__ b1,
                           const float* __restrict__ W2, int n) {
    int node = blockIdx.x * blockDim.x + threadIdx.x;
    if (node >= n) return;
    float di = g_dinv[node];
    float sl = di * di;  // self-loop norm
    const float4* a4 = (const float4*)(g_agg1 + node * H1);
    const float4* h4 = (const float4*)(g_h1 + node * H1);
    float z[H1];
#pragma unroll
    for (int q = 0; q < 4; q++) {
        float4 a = a4[q];
        float4 h = h4[q];
        z[q * 4 + 0] = fmaxf(a.x + sl * h.x + b1[q * 4 + 0], 0.f);
        z[q * 4 + 1] = fmaxf(a.y + sl * h.y + b1[q * 4 + 1], 0.f);
        z[q * 4 + 2] = fmaxf(a.z + sl * h.z + b1[q * 4 + 2], 0.f);
        z[q * 4 + 3] = fmaxf(a.w + sl * h.w + b1[q * 4 + 3], 0.f);
    }
    float o0 = 0.f, o1 = 0.f;
#pragma unroll
    for (int j = 0; j < H1; j++) {
        o0 += z[j] * W2[j * 2 + 0];
        o1 += z[j] * W2[j * 2 + 1];
    }
    float2* out = (float2*)(g_h2 + node * 2);
    *out = make_float2(o0, o1);
}

// ---------------- layer-2 edge scatter ----------------
__global__ void k_scatter2(int E) {
    int i = blockIdx.x * blockDim.x + threadIdx.x;
    if (i >= E) return;
    int s = g_src[i], d = g_dst[i];
    float norm = g_dinv[s] * g_dinv[d];
    float2 v = *(const float2*)(g_h2 + s * 2);
    float a = norm * v.x, b = norm * v.y;
    asm volatile("red.global.add.v2.f32 [%0], {%1, %2};" ::"l"(g_agg2 + d * 2),
                 "f"(a), "f"(b)
                 : "memory");
}

// ---------------- combine2 + log_softmax ----------------
__global__ void k_final(const float* __restrict__ b2, float* __restrict__ out,
                        int n) {
    int node = blockIdx.x * blockDim.x + threadIdx.x;
    if (node >= n) return;
    float di = g_dinv[node];
    float sl = di * di;
    float2 a = *(const float2*)(g_agg2 + node * 2);
    float2 h = *(const float2*)(g_h2 + node * 2);
    float o0 = a.x + sl * h.x + b2[0];
    float o1 = a.y + sl * h.y + b2[1];
    float m = fmaxf(o0, o1);
    float lse = m + logf(expf(o0 - m) + expf(o1 - m));
    float2* o = (float2*)(out + node * 2);
    *o = make_float2(o0 - lse, o1 - lse);
}

extern "C" void kernel_launch(void* const* d_in, const int* in_sizes, int n_in,
                              void* d_out, int out_size) {
    const float* x = (const float*)d_in[0];
    const void* ei = d_in[1];
    const float* W1 = (const float*)d_in[2];
    const float* b1 = (const float*)d_in[3];
    const float* W2 = (const float*)d_in[4];
    const float* b2 = (const float*)d_in[5];
    float* out = (float*)d_out;

    const int n = in_sizes[0] / F_IN;     // 200000
    const int E = in_sizes[1] / 2;        // 6400000

    const int TB = 256;
    const int eBlocks = (E + TB - 1) / TB;
    const int nBlocks = (n + TB - 1) / TB;
    const int wBlocks = (n + (TB / 32) - 1) / (TB / 32);  // warp per node

    k_zero<<<2048, TB>>>();
    k_detect<<<1, 256>>>(ei);
    k_convert<<<eBlocks, TB>>>(ei, E);
    k_dinv<<<nBlocks, TB>>>(n);
    k_h1<<<wBlocks, TB>>>(x, W1, n);
    k_scatter1<<<eBlocks, TB>>>(E);
    k_combine1<<<nBlocks, TB>>>(b1, W2, n);
    k_scatter2<<<eBlocks, TB>>>(E);
    k_final<<<nBlocks, TB>>>(b2, out, n);
}

// round 4
// speedup vs baseline: 1.3212x; 1.3212x over previous
#include <cuda_runtime.h>
#include <cuda_bf16.h>
#include <math.h>

#define N_NODES 200000
#define N_EDGES 6400000
#define F_IN    128
#define H1      16
#define C2      2

// ---------------- device scratch (no allocations allowed) ----------------
__device__ int   g_deg[N_NODES];      // in-degree
__device__ int   g_start[N_NODES];    // CSR segment start (arbitrary order)
__device__ int   g_cursor[N_NODES];   // placement cursors
__device__ float g_dinv[N_NODES];     // 1/sqrt(deg+1)
__device__ int   g_csr[N_EDGES];      // src ids grouped by dst
__device__ float g_h1s[N_NODES * H1]; // dinv * (x @ W1)
__device__ float g_h2s[N_NODES * C2]; // dinv * h2
__device__ int   g_total;             // segment allocator
__device__ int   g_is64;

// ---------------- zero degree counters + allocator ----------------
__global__ void k_zero() {
    int i = blockIdx.x * blockDim.x + threadIdx.x;
    if (i < N_NODES) g_deg[i] = 0;
    if (i == 0) g_total = 0;
}

// ---------------- detect int64 vs int32 edge_index ----------------
// int64 indices in [0, N_NODES) have zero upper words; an int32 buffer viewed
// as int64 combines adjacent random ints and leaves range with p ~= 1.
__global__ void k_detect(const void* __restrict__ ei) {
    __shared__ int bad;
    if (threadIdx.x == 0) bad = 0;
    __syncthreads();
    const long long* p = (const long long*)ei;
    for (int i = threadIdx.x; i < 1024; i += blockDim.x) {
        long long v = __ldg(p + i);
        if (v < 0 || v >= (long long)N_NODES) bad = 1;
    }
    __syncthreads();
    if (threadIdx.x == 0) g_is64 = bad ? 0 : 1;
}

// ---------------- in-degree count ----------------
__global__ void k_deg(const void* __restrict__ ei, int E) {
    int i = blockIdx.x * blockDim.x + threadIdx.x;
    if (i >= E) return;
    int d;
    if (g_is64) d = (int)__ldg((const long long*)ei + E + i);
    else        d = __ldg((const int*)ei + E + i);
    atomicAdd(&g_deg[d], 1);
}

// ---------------- segment assignment (block-aggregated allocator) --------
// Segment ORDER across nodes is irrelevant — only disjoint contiguous
// segments are needed — so a per-block atomicAdd on a global counter
// replaces a device-wide prefix scan.
__global__ void k_assign(int n) {
    int i = blockIdx.x * blockDim.x + threadIdx.x;
    int lane = threadIdx.x & 31;
    int warp = threadIdx.x >> 5;
    int deg = (i < n) ? g_deg[i] : 0;

    int v = deg;
#pragma unroll
    for (int off = 1; off < 32; off <<= 1) {
        int t = __shfl_up_sync(0xffffffff, v, off);
        if (lane >= off) v += t;
    }
    __shared__ int wsum[8];
    if (lane == 31) wsum[warp] = v;
    __syncthreads();
    if (warp == 0 && lane < 8) {
        int w = wsum[lane];
#pragma unroll
        for (int off = 1; off < 8; off <<= 1) {
            int t = __shfl_up_sync(0xff, w, off, 8);
            if (lane >= off) w += t;
        }
        wsum[lane] = w;
    }
    __syncthreads();
    int blockExcl = (warp ? wsum[warp - 1] : 0) + (v - deg);
    int blockTotal = wsum[7];
    __shared__ int base;
    if (threadIdx.x == 0) base = atomicAdd(&g_total, blockTotal);
    __syncthreads();
    if (i < n) {
        int s = base + blockExcl;
        g_start[i] = s;
        g_cursor[i] = s;
        g_dinv[i] = rsqrtf((float)deg + 1.0f);
    }
}

// ---------------- CSR placement ----------------
__global__ void k_place(const void* __restrict__ ei, int E) {
    int i = blockIdx.x * blockDim.x + threadIdx.x;
    if (i >= E) return;
    int s, d;
    if (g_is64) {
        const long long* p = (const long long*)ei;
        s = (int)__ldg(p + i);
        d = (int)__ldg(p + E + i);
    } else {
        const int* p = (const int*)ei;
        s = __ldg(p + i);
        d = __ldg(p + E + i);
    }
    int pos = atomicAdd(&g_cursor[d], 1);
    g_csr[pos] = s;
}

// ---------------- h1s = dinv * (x @ W1)  (warp per node) ----------------
__global__ void k_h1(const float* __restrict__ x, const float* __restrict__ W1,
                     int n) {
    __shared__ float W1t[H1 * F_IN];  // transposed: [j][k]
    for (int t = threadIdx.x; t < F_IN * H1; t += blockDim.x) {
        int k = t / H1, j = t % H1;
        W1t[j * F_IN + k] = W1[t];
    }
    __syncthreads();

    int warp = (blockIdx.x * blockDim.x + threadIdx.x) >> 5;
    int lane = threadIdx.x & 31;
    if (warp >= n) return;

    float4 xv = ((const float4*)x)[warp * (F_IN / 4) + lane];

    float acc[H1];
#pragma unroll
    for (int j = 0; j < H1; j++) {
        float4 w = ((const float4*)W1t)[j * (F_IN / 4) + lane];
        acc[j] = xv.x * w.x + xv.y * w.y + xv.z * w.z + xv.w * w.w;
    }
#pragma unroll
    for (int off = 16; off; off >>= 1) {
#pragma unroll
        for (int j = 0; j < H1; j++)
            acc[j] += __shfl_xor_sync(0xffffffff, acc[j], off);
    }
    if (lane == 0) {
        float dn = g_dinv[warp];
        float4* o = (float4*)(g_h1s + warp * H1);
        o[0] = make_float4(dn * acc[0], dn * acc[1], dn * acc[2], dn * acc[3]);
        o[1] = make_float4(dn * acc[4], dn * acc[5], dn * acc[6], dn * acc[7]);
        o[2] = make_float4(dn * acc[8], dn * acc[9], dn * acc[10], dn * acc[11]);
        o[3] = make_float4(dn * acc[12], dn * acc[13], dn * acc[14], dn * acc[15]);
    }
}

// ---------------- layer-1 gather + bias + ReLU + @W2 + pre-scale ---------
// Warp per node: half-warp per edge, lane%16 = feature.
__global__ void k_gather1(const float* __restrict__ b1,
                          const float* __restrict__ W2, int n) {
    __shared__ float sW2[H1 * C2];
    __shared__ float sb1[H1];
    if (threadIdx.x < H1 * C2) sW2[threadIdx.x] = W2[threadIdx.x];
    if (threadIdx.x < H1) sb1[threadIdx.x] = b1[threadIdx.x];
    __syncthreads();

    int node = (blockIdx.x * blockDim.x + threadIdx.x) >> 5;
    int lane = threadIdx.x & 31;
    if (node >= n) return;

    int start = g_start[node];
    int deg = g_deg[node];
    int half = lane >> 4;
    int f = lane & 15;

    float acc = 0.f;
    int e = 0;
    for (; e + 2 <= deg; e += 2) {
        int src = g_csr[start + e + half];          // broadcast per half-warp
        acc += g_h1s[src * H1 + f];                 // 64B gather (L2-resident)
    }
    if (e < deg && half == 0) {
        int src = g_csr[start + e];
        acc += g_h1s[src * H1 + f];
    }
    acc += __shfl_down_sync(0xffffffff, acc, 16);   // lanes 0-15 hold sums

    float dn = g_dinv[node];
    float o0 = 0.f, o1 = 0.f;
    if (lane < H1) {
        float hs = g_h1s[node * H1 + lane];         // self-loop: dinv^2*h1 = dinv*h1s
        float z = fmaxf(dn * (acc + hs) + sb1[lane], 0.f);
        o0 = z * sW2[lane * 2 + 0];
        o1 = z * sW2[lane * 2 + 1];
    }
#pragma unroll
    for (int off = 8; off; off >>= 1) {
        o0 += __shfl_xor_sync(0xffffffff, o0, off);
        o1 += __shfl_xor_sync(0xffffffff, o1, off);
    }
    if (lane == 0) {
        float2* o = (float2*)(g_h2s + node * C2);
        *o = make_float2(dn * o0, dn * o1);          // pre-scale for layer 2
    }
}

// ---------------- layer-2 gather + bias + log_softmax ----------------
__global__ void k_gather2(const float* __restrict__ b2, float* __restrict__ out,
                          int n) {
    int node = (blockIdx.x * blockDim.x + threadIdx.x) >> 5;
    int lane = threadIdx.x & 31;
    if (node >= n) return;

    int start = g_start[node];
    int deg = g_deg[node];

    float ax = 0.f, ay = 0.f;
    for (int e = lane; e < deg; e += 32) {
        int src = g_csr[start + e];
        float2 v = *(const float2*)(g_h2s + src * C2);
        ax += v.x;
        ay += v.y;
    }
#pragma unroll
    for (int off = 16; off; off >>= 1) {
        ax += __shfl_xor_sync(0xffffffff, ax, off);
        ay += __shfl_xor_sync(0xffffffff, ay, off);
    }
    if (lane == 0) {
        float dn = g_dinv[node];
        float2 hs = *(const float2*)(g_h2s + node * C2);
        float o0 = dn * (ax + hs.x) + b2[0];
        float o1 = dn * (ay + hs.y) + b2[1];
        float m = fmaxf(o0, o1);
        float lse = m + logf(expf(o0 - m) + expf(o1 - m));
        float2* o = (float2*)(out + node * C2);
        *o = make_float2(o0 - lse, o1 - lse);
    }
}

extern "C" void kernel_launch(void* const* d_in, const int* in_sizes, int n_in,
                              void* d_out, int out_size) {
    const float* x = (const float*)d_in[0];
    const void* ei = d_in[1];
    const float* W1 = (const float*)d_in[2];
    const float* b1 = (const float*)d_in[3];
    const float* W2 = (const float*)d_in[4];
    const float* b2 = (const float*)d_in[5];
    float* out = (float*)d_out;

    const int n = in_sizes[0] / F_IN;   // 200000
    const int E = in_sizes[1] / 2;      // 6400000

    const int TB = 256;
    const int eBlocks = (E + TB - 1) / TB;
    const int nBlocks = (n + TB - 1) / TB;
    const int wBlocks = (n + (TB / 32) - 1) / (TB / 32);

    k_zero<<<nBlocks, TB>>>();
    k_detect<<<1, 256>>>(ei);
    k_deg<<<eBlocks, TB>>>(ei, E);
    k_assign<<<nBlocks, TB>>>(n);
    k_h1<<<wBlocks, TB>>>(x, W1, n);
    k_place<<<eBlocks, TB>>>(ei, E);
    k_gather1<<<wBlocks, TB>>>(b1, W2, n);
    k_gather2<<<wBlocks, TB>>>(b2, out, n);
}